// round 15
// baseline (speedup 1.0000x reference)
#include <cuda_runtime.h>
#include <cuda_fp16.h>
#include <cstdint>

// GalerkinConv via mma.sync fp16 single-limb GEMMs (sm_103 baseline ISA)
// B=16, C_IN=128, C_OUT=128, N=16384, MODES=128
#define BB 16
#define CI 128
#define CO 128
#define NPTS 16384
#define KM 128
#define NSPLIT 64
#define KCH (NPTS / NSPLIT)   // 256 n per GEMM1 CTA
#define KBLK 64
#define NITER (KCH / KBLK)    // 4

// ---------------- scratch (static device globals; no allocation) ----------
__device__ __half g_part[NSPLIT * BB * CI * KM];   // fp16 partials, 33.6 MB
__device__ float  g_xco [BB * CI * KM];
__device__ __half g_xhat[BB * CO * KM];            // x_hat fp16, [b][o][k]
__device__ __half g_wbT [KM * NPTS];               // wbases^T fp16, [mode][n]
__device__ __half g_ba  [NPTS * KM];               // bases fp16, [n][k]

// ---------------- helpers --------------------------------------------------
__device__ __forceinline__ uint32_t smem_u32(const void* p) {
    uint32_t a;
    asm("{ .reg .u64 t; cvta.to.shared.u64 t, %1; cvt.u32.u64 %0, t; }"
        : "=r"(a) : "l"(p));
    return a;
}

#define SWZ128(o) ((o) ^ (((o) >> 3) & 0x70))   // 128B rows
#define SWZ256(o) ((o) ^ (((o) >> 4) & 0x70))   // 256B rows

#define LDSM_X4(r0, r1, r2, r3, a) \
    asm volatile("ldmatrix.sync.aligned.m8n8.x4.shared.b16 {%0,%1,%2,%3}, [%4];" \
                 : "=r"(r0), "=r"(r1), "=r"(r2), "=r"(r3) : "r"(a))
#define LDSM_X2(r0, r1, a) \
    asm volatile("ldmatrix.sync.aligned.m8n8.x2.shared.b16 {%0,%1}, [%2];" \
                 : "=r"(r0), "=r"(r1) : "r"(a))

#define CP16(dst_u32, src_ptr) \
    asm volatile("cp.async.cg.shared.global [%0], [%1], 16;" \
                 :: "r"(dst_u32), "l"(src_ptr))
#define CP_COMMIT asm volatile("cp.async.commit_group;" ::: "memory")
#define CP_WAIT(n) asm volatile("cp.async.wait_group %0;" :: "n"(n) : "memory")

__device__ __forceinline__ void mma16816h(float* d, const uint32_t* a, const uint32_t* b) {
    asm volatile(
        "mma.sync.aligned.m16n8k16.row.col.f32.f16.f16.f32 "
        "{%0,%1,%2,%3}, {%4,%5,%6,%7}, {%8,%9}, {%0,%1,%2,%3};"
        : "+f"(d[0]), "+f"(d[1]), "+f"(d[2]), "+f"(d[3])
        : "r"(a[0]), "r"(a[1]), "r"(a[2]), "r"(a[3]), "r"(b[0]), "r"(b[1]));
}

__device__ __forceinline__ uint32_t pack2h(__half a, __half b) {
    return (uint32_t)__half_as_ushort(a) | ((uint32_t)__half_as_ushort(b) << 16);
}

// ---------------------------------------------------------------------------
// prep (merged): blocks [0,2048) transpose wbases -> wbT fp16;
//                blocks [2048,4096) convert bases -> fp16
// ---------------------------------------------------------------------------
__global__ __launch_bounds__(256) void prep_kernel(const float* __restrict__ wb,
                                                   const float* __restrict__ ba) {
    const int bid = blockIdx.x;
    const int tid = threadIdx.x;
    if (bid < 2048) {
        __shared__ float t[32][33];
        const int n0 = (bid & 511) * 32, k0 = (bid >> 9) * 32;
        const int tx = tid & 31, ty = tid >> 5;   // 32 x 8
        #pragma unroll
        for (int i = 0; i < 4; i++)
            t[ty + i * 8][tx] = wb[(size_t)(n0 + ty + i * 8) * KM + k0 + tx];
        __syncthreads();
        #pragma unroll
        for (int i = 0; i < 4; i++) {
            float v = t[tx][ty + i * 8];
            g_wbT[(size_t)(k0 + ty + i * 8) * NPTS + n0 + tx] = __float2half(v);
        }
    } else {
        int i = ((bid - 2048) * 256 + tid) * 4;
        float4 v = *(const float4*)(ba + i);
        *(uint2*)(g_ba + i) = make_uint2(
            pack2h(__float2half(v.x), __float2half(v.y)),
            pack2h(__float2half(v.z), __float2half(v.w)));
    }
}

// ---------------------------------------------------------------------------
// GEMM1: partial[s][b] = x[b,:,chunk] @ wbases-chunk
//   M=128(c) x N=128(modes) x K=256 in 4 blocks of 64, double-buffered.
//   Stage 32KB: A@0 B@16K.  2 CTAs/SM.  Grid 64x16=1024 for wave balance.
// ---------------------------------------------------------------------------
#define G1_STAGE 32768
#define G1_SMEM (2 * G1_STAGE)

__device__ __forceinline__ void g1_conva(char* smem, int st, const float* xb,
                                         int t, int tid) {
    char* base = smem + st * G1_STAGE;
    #pragma unroll
    for (int i = 0; i < 8; i++) {
        int e = tid + i * 256;            // 0..2047 granules
        int c = e >> 4, q = e & 15;
        float4 v = *(const float4*)(xb + (size_t)c * NPTS + t * KBLK + q * 4);
        uint32_t off = SWZ128((uint32_t)(c * 128 + q * 8));
        *(uint2*)(base + off) = make_uint2(
            pack2h(__float2half(v.x), __float2half(v.y)),
            pack2h(__float2half(v.z), __float2half(v.w)));
    }
}
__device__ __forceinline__ void g1_loadb(uint32_t sb, int st, const __half* w,
                                         int t, int tid) {
    uint32_t base = sb + st * G1_STAGE + 16384;
    #pragma unroll
    for (int i = 0; i < 4; i++) {
        int e = tid + i * 256;
        int r = e >> 3, g = e & 7;
        uint32_t off = SWZ128((uint32_t)(r * 128 + g * 16));
        CP16(base + off, w + (size_t)r * NPTS + t * KBLK + g * 8);
    }
}
__device__ __forceinline__ void g1_compute(uint32_t sb, int st, float acc[4][4][4],
                                           int m0, int n0, int lane) {
    const uint32_t base = sb + st * G1_STAGE;
    const int a_row = lane & 15, a_kh = lane >> 4;
    const int b_row = lane & 7,  b_kh = (lane >> 3) & 1;
    #pragma unroll
    for (int ks = 0; ks < 4; ks++) {
        uint32_t bv[4][2], a[4][4];
        #pragma unroll
        for (int ni = 0; ni < 4; ni++) {
            uint32_t off = SWZ128((uint32_t)((n0 + ni * 8 + b_row) * 128 + ks * 32 + b_kh * 16));
            LDSM_X2(bv[ni][0], bv[ni][1], base + 16384 + off);
        }
        #pragma unroll
        for (int mi = 0; mi < 4; mi++) {
            uint32_t off = SWZ128((uint32_t)((m0 + mi * 16 + a_row) * 128 + ks * 32 + a_kh * 16));
            LDSM_X4(a[mi][0], a[mi][1], a[mi][2], a[mi][3], base + off);
        }
        #pragma unroll
        for (int mi = 0; mi < 4; mi++)
            #pragma unroll
            for (int ni = 0; ni < 4; ni++) mma16816h(acc[mi][ni], a[mi], bv[ni]);
    }
}

__global__ __launch_bounds__(256, 2) void gemm1_kernel(const float* __restrict__ x) {
    extern __shared__ __align__(128) char smem[];
    const uint32_t sb = smem_u32(smem);
    const int s = blockIdx.x, b = blockIdx.y;
    const int tid = threadIdx.x, wid = tid >> 5, lane = tid & 31;
    const int m0 = (wid >> 2) * 64, n0 = (wid & 3) * 32;

    float acc[4][4][4];
    #pragma unroll
    for (int mi = 0; mi < 4; mi++)
        #pragma unroll
        for (int ni = 0; ni < 4; ni++)
            #pragma unroll
            for (int j = 0; j < 4; j++) acc[mi][ni][j] = 0.0f;

    const float* xb = x + (size_t)b * CI * NPTS + (size_t)s * KCH;
    const __half* w = g_wbT + (size_t)s * KCH;

    g1_loadb(sb, 0, w, 0, tid); CP_COMMIT;
    g1_conva(smem, 0, xb, 0, tid);
    CP_WAIT(0);
    __syncthreads();

    for (int t = 0; t < NITER; t++) {
        const int cur = t & 1, nxt = cur ^ 1;
        if (t + 1 < NITER) { g1_loadb(sb, nxt, w, t + 1, tid); CP_COMMIT; }
        g1_compute(sb, cur, acc, m0, n0, lane);
        if (t + 1 < NITER) {
            g1_conva(smem, nxt, xb, t + 1, tid);
            CP_WAIT(0);
        }
        __syncthreads();
    }

    // epilogue -> fp16 partials
    const int gid = lane >> 2, tg = lane & 3;
    __half* dst = g_part + (size_t)(s * BB + b) * CI * KM;
    #pragma unroll
    for (int mi = 0; mi < 4; mi++)
        #pragma unroll
        for (int ni = 0; ni < 4; ni++) {
            int row = m0 + mi * 16 + gid;
            int col = n0 + ni * 8 + tg * 2;
            *(uint32_t*)(dst + (size_t)row * KM + col) =
                pack2h(__float2half(acc[mi][ni][0]), __float2half(acc[mi][ni][1]));
            *(uint32_t*)(dst + (size_t)(row + 8) * KM + col) =
                pack2h(__float2half(acc[mi][ni][2]), __float2half(acc[mi][ni][3]));
        }
}

// ---------------------------------------------------------------------------
// Deterministic split-K reduction: fp16 partials -> f32 xco
// ---------------------------------------------------------------------------
__global__ __launch_bounds__(128) void reduce_kernel() {
    int idx = (blockIdx.x * 128 + threadIdx.x) * 4;
    float4 s = make_float4(0.f, 0.f, 0.f, 0.f);
    #pragma unroll 8
    for (int p = 0; p < NSPLIT; p++) {
        uint2 v = *(const uint2*)(g_part + (size_t)p * (BB * CI * KM) + idx);
        __half2 h0 = *(__half2*)&v.x, h1 = *(__half2*)&v.y;
        float2 f0 = __half22float2(h0), f1 = __half22float2(h1);
        s.x += f0.x; s.y += f0.y; s.z += f1.x; s.w += f1.y;
    }
    *(float4*)(g_xco + idx) = s;
}

// ---------------------------------------------------------------------------
// mix: x_hat[b,o,k] = sum_i x_co[b,i,k] * W[i,o,k]; 2o x 2b tiles, 512 blocks
// ---------------------------------------------------------------------------
__global__ __launch_bounds__(128) void mix_kernel(const float* __restrict__ W) {
    const int o0 = blockIdx.x * 2, b0 = blockIdx.y * 2;   // grid (64, 8)
    const int k = threadIdx.x;
    float acc[2][2] = {{0.f, 0.f}, {0.f, 0.f}};

    for (int i = 0; i < CI; i++) {
        float wv[2], xv[2];
        #pragma unroll
        for (int oo = 0; oo < 2; oo++)
            wv[oo] = W[((size_t)i * CO + o0 + oo) * KM + k];
        #pragma unroll
        for (int bb = 0; bb < 2; bb++)
            xv[bb] = g_xco[((size_t)(b0 + bb) * CI + i) * KM + k];
        #pragma unroll
        for (int oo = 0; oo < 2; oo++)
            #pragma unroll
            for (int bb = 0; bb < 2; bb++)
                acc[oo][bb] = fmaf(xv[bb], wv[oo], acc[oo][bb]);
    }
    #pragma unroll
    for (int oo = 0; oo < 2; oo++)
        #pragma unroll
        for (int bb = 0; bb < 2; bb++)
            g_xhat[((size_t)(b0 + bb) * CO + o0 + oo) * KM + k] =
                __float2half(acc[oo][bb]);
}

// ---------------------------------------------------------------------------
// GEMM3: out[b, o, :] = x_hat[b] @ bases^T.  Grid (64, 16): each CTA loads
//   A (x_hat, 32KB) once + 2 jobs' B tiles via cp.async.
//   smem: A@0, B[j]@32K + j*32K.  Total 96KB -> 2 CTAs/SM.
// ---------------------------------------------------------------------------
#define G3_B0 32768
#define G3_BST 32768
#define G3_SMEM (G3_B0 + 2 * G3_BST)   // 98304

__global__ __launch_bounds__(256, 2) void gemm3_kernel(float* __restrict__ out) {
    extern __shared__ __align__(128) char smem[];
    const uint32_t sb = smem_u32(smem);
    const int bx = blockIdx.x, b = blockIdx.y;
    const int tid = threadIdx.x, wid = tid >> 5, lane = tid & 31;
    const int m0 = (wid >> 2) * 64, n0 = (wid & 3) * 32;

    // A: x_hat [128 o x 128 k], 256B rows, swizzled (group 0, with B0)
    const __half* xh = g_xhat + (size_t)b * CO * KM;
    #pragma unroll
    for (int i = 0; i < 8; i++) {
        int e = tid + i * 256;
        int r = e >> 4, g = e & 15;
        uint32_t off = SWZ256((uint32_t)(r * 256 + g * 16));
        CP16(sb + off, xh + (size_t)r * KM + g * 8);
    }
    // B jobs 0..1, one commit group each
    #pragma unroll
    for (int j = 0; j < 2; j++) {
        const int x0 = (bx * 2 + j) * 128;
        uint32_t base = sb + G3_B0 + j * G3_BST;
        #pragma unroll
        for (int i = 0; i < 8; i++) {
            int e = tid + i * 256;
            int r = e >> 4, g = e & 15;
            uint32_t off = SWZ256((uint32_t)(r * 256 + g * 16));
            CP16(base + off, g_ba + (size_t)(x0 + r) * KM + g * 8);
        }
        CP_COMMIT;
    }

    const int a_row = lane & 15, a_kh = lane >> 4;
    const int b_row = lane & 7,  b_kh = (lane >> 3) & 1;
    const int gid = lane >> 2, tg = lane & 3;

    for (int j = 0; j < 2; j++) {
        if (j == 0) { CP_WAIT(1); } else { CP_WAIT(0); }
        __syncthreads();

        const uint32_t bbase = sb + G3_B0 + j * G3_BST;
        float acc[4][4][4];
        #pragma unroll
        for (int mi = 0; mi < 4; mi++)
            #pragma unroll
            for (int ni = 0; ni < 4; ni++)
                #pragma unroll
                for (int q = 0; q < 4; q++) acc[mi][ni][q] = 0.0f;

        #pragma unroll
        for (int ks = 0; ks < 8; ks++) {
            uint32_t a[4][4], bv[4][2];
            #pragma unroll
            for (int mi = 0; mi < 4; mi++) {
                uint32_t off = SWZ256((uint32_t)((m0 + mi * 16 + a_row) * 256 + ks * 32 + a_kh * 16));
                LDSM_X4(a[mi][0], a[mi][1], a[mi][2], a[mi][3], sb + off);
            }
            #pragma unroll
            for (int ni = 0; ni < 4; ni++) {
                uint32_t off = SWZ256((uint32_t)((n0 + ni * 8 + b_row) * 256 + ks * 32 + b_kh * 16));
                LDSM_X2(bv[ni][0], bv[ni][1], bbase + off);
            }
            #pragma unroll
            for (int mi = 0; mi < 4; mi++)
                #pragma unroll
                for (int ni = 0; ni < 4; ni++) mma16816h(acc[mi][ni], a[mi], bv[ni]);
        }

        const int x0 = (bx * 2 + j) * 128;
        float* ob = out + (size_t)b * CO * NPTS + x0;
        #pragma unroll
        for (int mi = 0; mi < 4; mi++)
            #pragma unroll
            for (int ni = 0; ni < 4; ni++) {
                int row = m0 + mi * 16 + gid;
                int col = n0 + ni * 8 + tg * 2;
                *(float2*)(ob + (size_t)row * NPTS + col) =
                    make_float2(acc[mi][ni][0], acc[mi][ni][1]);
                *(float2*)(ob + (size_t)(row + 8) * NPTS + col) =
                    make_float2(acc[mi][ni][2], acc[mi][ni][3]);
            }
    }
}

// ---------------------------------------------------------------------------
extern "C" void kernel_launch(void* const* d_in, const int* in_sizes, int n_in,
                              void* d_out, int out_size) {
    const float* x  = (const float*)d_in[0];   // [16,128,16384]
    const float* wb = (const float*)d_in[1];   // wbases [16384,128]
    const float* ba = (const float*)d_in[2];   // bases  [16384,128]
    const float* W  = (const float*)d_in[3];   // [128,128,128]
    float* out = (float*)d_out;                // [16,128,16384]

    cudaFuncSetAttribute(gemm1_kernel, cudaFuncAttributeMaxDynamicSharedMemorySize, G1_SMEM);
    cudaFuncSetAttribute(gemm3_kernel, cudaFuncAttributeMaxDynamicSharedMemorySize, G3_SMEM);

    prep_kernel<<<4096, 256>>>(wb, ba);
    gemm1_kernel<<<dim3(NSPLIT, BB), 256, G1_SMEM>>>(x);
    reduce_kernel<<<(BB * CI * KM) / 512, 128>>>();
    mix_kernel<<<dim3(CO / 2, BB / 2), 128>>>(W);
    gemm3_kernel<<<dim3(NPTS / 256, BB), 256, G3_SMEM>>>(out);
}

// round 17
// speedup vs baseline: 1.0704x; 1.0704x over previous
#include <cuda_runtime.h>
#include <cuda_fp16.h>
#include <cstdint>

// GalerkinConv via mma.sync fp16 single-limb GEMMs (sm_103 baseline ISA)
// B=16, C_IN=128, C_OUT=128, N=16384, MODES=128
#define BB 16
#define CI 128
#define CO 128
#define NPTS 16384
#define KM 128
#define NSPLIT 16
#define KCH (NPTS / NSPLIT)   // 1024 n per GEMM1 CTA
#define KBLK 64
#define NITER (KCH / KBLK)    // 16

// ---------------- scratch (static device globals; no allocation) ----------
__device__ __half g_part[NSPLIT * BB * CI * KM];   // fp16 partials, 8.4 MB
__device__ float  g_xco [BB * CI * KM];
__device__ __half g_xhat[BB * CO * KM];            // x_hat fp16, [b][o][k]
__device__ __half g_wbT [KM * NPTS];               // wbases^T fp16, [mode][n]
__device__ __half g_ba  [NPTS * KM];               // bases fp16, [n][k]

// ---------------- helpers --------------------------------------------------
__device__ __forceinline__ uint32_t smem_u32(const void* p) {
    uint32_t a;
    asm("{ .reg .u64 t; cvta.to.shared.u64 t, %1; cvt.u32.u64 %0, t; }"
        : "=r"(a) : "l"(p));
    return a;
}

#define SWZ128(o) ((o) ^ (((o) >> 3) & 0x70))   // 128B rows
#define SWZ256(o) ((o) ^ (((o) >> 4) & 0x70))   // 256B rows

#define LDSM_X4(r0, r1, r2, r3, a) \
    asm volatile("ldmatrix.sync.aligned.m8n8.x4.shared.b16 {%0,%1,%2,%3}, [%4];" \
                 : "=r"(r0), "=r"(r1), "=r"(r2), "=r"(r3) : "r"(a))
#define LDSM_X2(r0, r1, a) \
    asm volatile("ldmatrix.sync.aligned.m8n8.x2.shared.b16 {%0,%1}, [%2];" \
                 : "=r"(r0), "=r"(r1) : "r"(a))

#define CP16(dst_u32, src_ptr) \
    asm volatile("cp.async.cg.shared.global [%0], [%1], 16;" \
                 :: "r"(dst_u32), "l"(src_ptr))
#define CP_COMMIT asm volatile("cp.async.commit_group;" ::: "memory")
#define CP_WAIT(n) asm volatile("cp.async.wait_group %0;" :: "n"(n) : "memory")

__device__ __forceinline__ void mma16816h(float* d, const uint32_t* a, const uint32_t* b) {
    asm volatile(
        "mma.sync.aligned.m16n8k16.row.col.f32.f16.f16.f32 "
        "{%0,%1,%2,%3}, {%4,%5,%6,%7}, {%8,%9}, {%0,%1,%2,%3};"
        : "+f"(d[0]), "+f"(d[1]), "+f"(d[2]), "+f"(d[3])
        : "r"(a[0]), "r"(a[1]), "r"(a[2]), "r"(a[3]), "r"(b[0]), "r"(b[1]));
}

__device__ __forceinline__ uint32_t pack2h(__half a, __half b) {
    return (uint32_t)__half_as_ushort(a) | ((uint32_t)__half_as_ushort(b) << 16);
}

// ---------------------------------------------------------------------------
// prep (merged): blocks [0,2048) transpose wbases -> wbT fp16;
//                blocks [2048,4096) convert bases -> fp16
// ---------------------------------------------------------------------------
__global__ __launch_bounds__(256) void prep_kernel(const float* __restrict__ wb,
                                                   const float* __restrict__ ba) {
    const int bid = blockIdx.x;
    const int tid = threadIdx.x;
    if (bid < 2048) {
        __shared__ float t[32][33];
        const int n0 = (bid & 511) * 32, k0 = (bid >> 9) * 32;
        const int tx = tid & 31, ty = tid >> 5;   // 32 x 8
        #pragma unroll
        for (int i = 0; i < 4; i++)
            t[ty + i * 8][tx] = wb[(size_t)(n0 + ty + i * 8) * KM + k0 + tx];
        __syncthreads();
        #pragma unroll
        for (int i = 0; i < 4; i++) {
            float v = t[tx][ty + i * 8];
            g_wbT[(size_t)(k0 + ty + i * 8) * NPTS + n0 + tx] = __float2half(v);
        }
    } else {
        int i = ((bid - 2048) * 256 + tid) * 4;
        float4 v = *(const float4*)(ba + i);
        *(uint2*)(g_ba + i) = make_uint2(
            pack2h(__float2half(v.x), __float2half(v.y)),
            pack2h(__float2half(v.z), __float2half(v.w)));
    }
}

// ---------------------------------------------------------------------------
// GEMM1: partial[s][b] = x[b,:,chunk] @ wbases-chunk
//   M=128(c) x N=128(modes) x K=1024 in 16 blocks of 64, double-buffered.
//   Stage 32KB: A@0 B@16K.  2 CTAs/SM.
// ---------------------------------------------------------------------------
#define G1_STAGE 32768
#define G1_SMEM (2 * G1_STAGE)

__device__ __forceinline__ void g1_conva(char* smem, int st, const float* xb,
                                         int t, int tid) {
    char* base = smem + st * G1_STAGE;
    #pragma unroll
    for (int i = 0; i < 8; i++) {
        int e = tid + i * 256;            // 0..2047 granules
        int c = e >> 4, q = e & 15;
        float4 v = *(const float4*)(xb + (size_t)c * NPTS + t * KBLK + q * 4);
        uint32_t off = SWZ128((uint32_t)(c * 128 + q * 8));
        *(uint2*)(base + off) = make_uint2(
            pack2h(__float2half(v.x), __float2half(v.y)),
            pack2h(__float2half(v.z), __float2half(v.w)));
    }
}
__device__ __forceinline__ void g1_loadb(uint32_t sb, int st, const __half* w,
                                         int t, int tid) {
    uint32_t base = sb + st * G1_STAGE + 16384;
    #pragma unroll
    for (int i = 0; i < 4; i++) {
        int e = tid + i * 256;
        int r = e >> 3, g = e & 7;
        uint32_t off = SWZ128((uint32_t)(r * 128 + g * 16));
        CP16(base + off, w + (size_t)r * NPTS + t * KBLK + g * 8);
    }
}
__device__ __forceinline__ void g1_compute(uint32_t sb, int st, float acc[4][4][4],
                                           int m0, int n0, int lane) {
    const uint32_t base = sb + st * G1_STAGE;
    const int a_row = lane & 15, a_kh = lane >> 4;
    const int b_row = lane & 7,  b_kh = (lane >> 3) & 1;
    #pragma unroll
    for (int ks = 0; ks < 4; ks++) {
        uint32_t bv[4][2], a[4][4];
        #pragma unroll
        for (int ni = 0; ni < 4; ni++) {
            uint32_t off = SWZ128((uint32_t)((n0 + ni * 8 + b_row) * 128 + ks * 32 + b_kh * 16));
            LDSM_X2(bv[ni][0], bv[ni][1], base + 16384 + off);
        }
        #pragma unroll
        for (int mi = 0; mi < 4; mi++) {
            uint32_t off = SWZ128((uint32_t)((m0 + mi * 16 + a_row) * 128 + ks * 32 + a_kh * 16));
            LDSM_X4(a[mi][0], a[mi][1], a[mi][2], a[mi][3], base + off);
        }
        #pragma unroll
        for (int mi = 0; mi < 4; mi++)
            #pragma unroll
            for (int ni = 0; ni < 4; ni++) mma16816h(acc[mi][ni], a[mi], bv[ni]);
    }
}

__global__ __launch_bounds__(256, 2) void gemm1_kernel(const float* __restrict__ x) {
    extern __shared__ __align__(128) char smem[];
    const uint32_t sb = smem_u32(smem);
    const int s = blockIdx.x, b = blockIdx.y;
    const int tid = threadIdx.x, wid = tid >> 5, lane = tid & 31;
    const int m0 = (wid >> 2) * 64, n0 = (wid & 3) * 32;

    float acc[4][4][4];
    #pragma unroll
    for (int mi = 0; mi < 4; mi++)
        #pragma unroll
        for (int ni = 0; ni < 4; ni++)
            #pragma unroll
            for (int j = 0; j < 4; j++) acc[mi][ni][j] = 0.0f;

    const float* xb = x + (size_t)b * CI * NPTS + (size_t)s * KCH;
    const __half* w = g_wbT + (size_t)s * KCH;

    g1_loadb(sb, 0, w, 0, tid); CP_COMMIT;
    g1_conva(smem, 0, xb, 0, tid);
    CP_WAIT(0);
    __syncthreads();

    for (int t = 0; t < NITER; t++) {
        const int cur = t & 1, nxt = cur ^ 1;
        if (t + 1 < NITER) { g1_loadb(sb, nxt, w, t + 1, tid); CP_COMMIT; }
        g1_compute(sb, cur, acc, m0, n0, lane);
        if (t + 1 < NITER) {
            g1_conva(smem, nxt, xb, t + 1, tid);
            CP_WAIT(0);
        }
        __syncthreads();
    }

    // epilogue -> fp16 partials
    const int gid = lane >> 2, tg = lane & 3;
    __half* dst = g_part + (size_t)(s * BB + b) * CI * KM;
    #pragma unroll
    for (int mi = 0; mi < 4; mi++)
        #pragma unroll
        for (int ni = 0; ni < 4; ni++) {
            int row = m0 + mi * 16 + gid;
            int col = n0 + ni * 8 + tg * 2;
            *(uint32_t*)(dst + (size_t)row * KM + col) =
                pack2h(__float2half(acc[mi][ni][0]), __float2half(acc[mi][ni][1]));
            *(uint32_t*)(dst + (size_t)(row + 8) * KM + col) =
                pack2h(__float2half(acc[mi][ni][2]), __float2half(acc[mi][ni][3]));
        }
}

// ---------------------------------------------------------------------------
// Deterministic split-K reduction: fp16 partials -> f32 xco
// ---------------------------------------------------------------------------
__global__ __launch_bounds__(128) void reduce_kernel() {
    int idx = (blockIdx.x * 128 + threadIdx.x) * 4;
    float4 s = make_float4(0.f, 0.f, 0.f, 0.f);
    #pragma unroll
    for (int p = 0; p < NSPLIT; p++) {
        uint2 v = *(const uint2*)(g_part + (size_t)p * (BB * CI * KM) + idx);
        __half2 h0 = *(__half2*)&v.x, h1 = *(__half2*)&v.y;
        float2 f0 = __half22float2(h0), f1 = __half22float2(h1);
        s.x += f0.x; s.y += f0.y; s.z += f1.x; s.w += f1.y;
    }
    *(float4*)(g_xco + idx) = s;
}

// ---------------------------------------------------------------------------
// mix: x_hat[b,o,k] = sum_i x_co[b,i,k] * W[i,o,k]; 2o x 2b tiles,
//   i-loop unrolled x8 with upfront load batches (32 outstanding loads).
// ---------------------------------------------------------------------------
__global__ __launch_bounds__(128) void mix_kernel(const float* __restrict__ W) {
    const int o0 = blockIdx.x * 2, b0 = blockIdx.y * 2;   // grid (64, 8)
    const int k = threadIdx.x;
    float acc00 = 0.f, acc01 = 0.f, acc10 = 0.f, acc11 = 0.f;

    const float* wp = W + (size_t)o0 * KM + k;            // + i*CO*KM
    const float* xp = g_xco + (size_t)b0 * CI * KM + k;   // + i*KM

    for (int i0 = 0; i0 < CI; i0 += 8) {
        float w0[8], w1[8], x0[8], x1[8];
        #pragma unroll
        for (int u = 0; u < 8; u++) {
            size_t iw = (size_t)(i0 + u) * CO * KM;
            w0[u] = __ldg(wp + iw);
            w1[u] = __ldg(wp + iw + KM);
        }
        #pragma unroll
        for (int u = 0; u < 8; u++) {
            size_t ix = (size_t)(i0 + u) * KM;
            x0[u] = xp[ix];
            x1[u] = xp[ix + (size_t)CI * KM];
        }
        #pragma unroll
        for (int u = 0; u < 8; u++) {
            acc00 = fmaf(x0[u], w0[u], acc00);
            acc01 = fmaf(x0[u], w1[u], acc01);
            acc10 = fmaf(x1[u], w0[u], acc10);
            acc11 = fmaf(x1[u], w1[u], acc11);
        }
    }
    size_t base = ((size_t)b0 * CO + o0) * KM + k;
    g_xhat[base]                       = __float2half(acc00);
    g_xhat[base + KM]                  = __float2half(acc01);
    g_xhat[base + (size_t)CO * KM]      = __float2half(acc10);
    g_xhat[base + (size_t)CO * KM + KM] = __float2half(acc11);
}

// ---------------------------------------------------------------------------
// GEMM3: out[b, o, :] = x_hat[b] @ bases^T.  Grid (64, 16): each CTA loads
//   A (x_hat, 32KB) once + 2 jobs' B tiles via cp.async.
//   smem: A@0, B[j]@32K + j*32K.  Total 96KB -> 2 CTAs/SM.
// ---------------------------------------------------------------------------
#define G3_B0 32768
#define G3_BST 32768
#define G3_SMEM (G3_B0 + 2 * G3_BST)   // 98304

__global__ __launch_bounds__(256, 2) void gemm3_kernel(float* __restrict__ out) {
    extern __shared__ __align__(128) char smem[];
    const uint32_t sb = smem_u32(smem);
    const int bx = blockIdx.x, b = blockIdx.y;
    const int tid = threadIdx.x, wid = tid >> 5, lane = tid & 31;
    const int m0 = (wid >> 2) * 64, n0 = (wid & 3) * 32;

    // A: x_hat [128 o x 128 k], 256B rows, swizzled (group 0, with B0)
    const __half* xh = g_xhat + (size_t)b * CO * KM;
    #pragma unroll
    for (int i = 0; i < 8; i++) {
        int e = tid + i * 256;
        int r = e >> 4, g = e & 15;
        uint32_t off = SWZ256((uint32_t)(r * 256 + g * 16));
        CP16(sb + off, xh + (size_t)r * KM + g * 8);
    }
    // B jobs 0..1, one commit group each
    #pragma unroll
    for (int j = 0; j < 2; j++) {
        const int x0 = (bx * 2 + j) * 128;
        uint32_t base = sb + G3_B0 + j * G3_BST;
        #pragma unroll
        for (int i = 0; i < 8; i++) {
            int e = tid + i * 256;
            int r = e >> 4, g = e & 15;
            uint32_t off = SWZ256((uint32_t)(r * 256 + g * 16));
            CP16(base + off, g_ba + (size_t)(x0 + r) * KM + g * 8);
        }
        CP_COMMIT;
    }

    const int a_row = lane & 15, a_kh = lane >> 4;
    const int b_row = lane & 7,  b_kh = (lane >> 3) & 1;
    const int gid = lane >> 2, tg = lane & 3;

    for (int j = 0; j < 2; j++) {
        if (j == 0) { CP_WAIT(1); } else { CP_WAIT(0); }
        __syncthreads();

        const uint32_t bbase = sb + G3_B0 + j * G3_BST;
        float acc[4][4][4];
        #pragma unroll
        for (int mi = 0; mi < 4; mi++)
            #pragma unroll
            for (int ni = 0; ni < 4; ni++)
                #pragma unroll
                for (int q = 0; q < 4; q++) acc[mi][ni][q] = 0.0f;

        #pragma unroll
        for (int ks = 0; ks < 8; ks++) {
            uint32_t a[4][4], bv[4][2];
            #pragma unroll
            for (int mi = 0; mi < 4; mi++) {
                uint32_t off = SWZ256((uint32_t)((m0 + mi * 16 + a_row) * 256 + ks * 32 + a_kh * 16));
                LDSM_X4(a[mi][0], a[mi][1], a[mi][2], a[mi][3], sb + off);
            }
            #pragma unroll
            for (int ni = 0; ni < 4; ni++) {
                uint32_t off = SWZ256((uint32_t)((n0 + ni * 8 + b_row) * 256 + ks * 32 + b_kh * 16));
                LDSM_X2(bv[ni][0], bv[ni][1], bbase + off);
            }
            #pragma unroll
            for (int mi = 0; mi < 4; mi++)
                #pragma unroll
                for (int ni = 0; ni < 4; ni++) mma16816h(acc[mi][ni], a[mi], bv[ni]);
        }

        const int x0 = (bx * 2 + j) * 128;
        float* ob = out + (size_t)b * CO * NPTS + x0;
        #pragma unroll
        for (int mi = 0; mi < 4; mi++)
            #pragma unroll
            for (int ni = 0; ni < 4; ni++) {
                int row = m0 + mi * 16 + gid;
                int col = n0 + ni * 8 + tg * 2;
                *(float2*)(ob + (size_t)row * NPTS + col) =
                    make_float2(acc[mi][ni][0], acc[mi][ni][1]);
                *(float2*)(ob + (size_t)(row + 8) * NPTS + col) =
                    make_float2(acc[mi][ni][2], acc[mi][ni][3]);
            }
    }
}

// ---------------------------------------------------------------------------
extern "C" void kernel_launch(void* const* d_in, const int* in_sizes, int n_in,
                              void* d_out, int out_size) {
    const float* x  = (const float*)d_in[0];   // [16,128,16384]
    const float* wb = (const float*)d_in[1];   // wbases [16384,128]
    const float* ba = (const float*)d_in[2];   // bases  [16384,128]
    const float* W  = (const float*)d_in[3];   // [128,128,128]
    float* out = (float*)d_out;                // [16,128,16384]

    cudaFuncSetAttribute(gemm1_kernel, cudaFuncAttributeMaxDynamicSharedMemorySize, G1_SMEM);
    cudaFuncSetAttribute(gemm3_kernel, cudaFuncAttributeMaxDynamicSharedMemorySize, G3_SMEM);

    prep_kernel<<<4096, 256>>>(wb, ba);
    gemm1_kernel<<<dim3(NSPLIT, BB), 256, G1_SMEM>>>(x);
    reduce_kernel<<<(BB * CI * KM) / 512, 128>>>();
    mix_kernel<<<dim3(CO / 2, BB / 2), 128>>>(W);
    gemm3_kernel<<<dim3(NPTS / 256, BB), 256, G3_SMEM>>>(out);
}